// round 10
// baseline (speedup 1.0000x reference)
#include <cuda_runtime.h>
#include <cstdint>

#define TOTAL    488418
#define BATCHN   10
#define NPROB    80
#define HID      256
#define OUT_TOTAL (BATCHN*TOTAL)
#define MAXEQ2   4096
#define NBIN     16384            /* 14-bit buckets */
#define BSHIFT   18               /* bin = key >> 18 */
#define NCHUNK   35               /* chunk descriptors per batch */
#define CHUNK    16384
#define HIST_SMEM (8*NBIN)        /* 128 KB: 8 warp-private u8 hists */

// slice column boundaries
#define B1 160000
#define B2 160400
#define B3 320400
#define B4 320800
#define B5 480800
#define B6 481200
#define B7 488400

__constant__ int c_sln[8] = {160000,400,160000,400,160000,400,7200,18};
__constant__ int c_slo[8] = {0,B1,B2,B3,B4,B5,B6,B7};
__constant__ int c_ob[8]  = {0,10*B1,10*B2,10*B3,10*B4,10*B5,10*B6,10*B7};
__constant__ int c_dlo[8] = {0,10,11,21,22,32,33,34};   // chunk range per slice
__constant__ int c_dhi[8] = {9,10,20,21,31,32,33,34};

__device__ float    g_h[BATCHN*HID];
__device__ unsigned g_keys[BATCHN*TOTAL];               // 19.5 MB
__device__ unsigned g_chist16[BATCHN*NCHUNK*(NBIN/2)];  // 11.5 MB u16-packed chunk hists
__device__ unsigned g_T14[NPROB];
__device__ int      g_kkp[NPROB];
__device__ int      g_ccnt[NPROB];
__device__ unsigned g_ck[NPROB*MAXEQ2];
__device__ int      g_ci[NPROB*MAXEQ2];

// ---------------- threefry-2x32 (key=(0,42)), partitionable bits ----------------
__device__ __forceinline__ unsigned rotl(unsigned x, int d) {
    return __funnelshift_l(x, x, d);
}
__device__ __forceinline__ unsigned pbits(unsigned e) {
    const unsigned K0 = 0u, K1 = 42u, K2 = 0x1BD11BDAu ^ K0 ^ K1;
    unsigned x0 = 0u + K0, x1 = e + K1;
#define TFR(r) { x0 += x1; x1 = rotl(x1, (r)); x1 ^= x0; }
    TFR(13) TFR(15) TFR(26) TFR(6)   x0 += K1; x1 += K2 + 1u;
    TFR(17) TFR(29) TFR(16) TFR(24)  x0 += K2; x1 += K0 + 2u;
    TFR(13) TFR(15) TFR(26) TFR(6)   x0 += K0; x1 += K1 + 3u;
    TFR(17) TFR(29) TFR(16) TFR(24)  x0 += K1; x1 += K2 + 4u;
    TFR(13) TFR(15) TFR(26) TFR(6)   x0 += K2; x1 += K0 + 5u;
#undef TFR
    return x0 ^ x1;
}
__device__ __forceinline__ float gumbel_from_bits(unsigned bits) {
    float uf = __uint_as_float((bits >> 9) | 0x3F800000u) - 1.0f;
    uf = fmaxf(uf, 1.17549435e-38f);
    return -logf(-logf(uf));
}
__device__ __forceinline__ unsigned keymap(float z) {
    unsigned u = __float_as_uint(z);
    return u ^ (unsigned)(((int)u >> 31) | 0x80000000);
}

// ---------------- packed f32x2 helpers ----------------
__device__ __forceinline__ unsigned long long pack_dup(float x) {
    unsigned long long r; unsigned xi = __float_as_uint(x);
    asm("mov.b64 %0, {%1, %1};" : "=l"(r) : "r"(xi));
    return r;
}
__device__ __forceinline__ void fma2(unsigned long long &d,
                                     unsigned long long a, unsigned long long b) {
    asm("fma.rn.f32x2 %0, %1, %2, %0;" : "+l"(d) : "l"(a), "l"(b));
}
__device__ __forceinline__ void unpack2(unsigned long long v, float &lo, float &hi) {
    unsigned a, b;
    asm("mov.b64 {%0, %1}, %2;" : "=r"(a), "=r"(b) : "l"(v));
    lo = __uint_as_float(a); hi = __uint_as_float(b);
}

// chunk descriptor d in [0,35) -> (slice, start col, len)
__device__ __forceinline__ void chunk_desc(int d, int &s, int &start, int &len) {
    int i = 0;
    if (d < 10)       { s = 0; i = d; }
    else if (d == 10) { s = 1; }
    else if (d < 21)  { s = 2; i = d - 11; }
    else if (d == 21) { s = 3; }
    else if (d < 32)  { s = 4; i = d - 22; }
    else if (d == 32) { s = 5; }
    else if (d == 33) { s = 6; }
    else              { s = 7; }
    int n = c_sln[s];
    start = c_slo[s] + i*CHUNK;
    len = min(CHUNK, n - i*CHUNK);
}

// ---------------- no-op padding kernels (align ncu capture onto k_main) ----------------
__global__ void k_nop() {}

// ---------------- kernel 1: h = relu(emb @ W1 + b1) ----------------
__global__ void k_hidden(const float* __restrict__ emb,
                         const float* __restrict__ W1,
                         const float* __restrict__ b1) {
    __shared__ float se[BATCHN*10];
    int j = threadIdx.x;                // 256 threads
    if (j < BATCHN*10) se[j] = emb[j];
    __syncthreads();
    float bj = b1[j];
#pragma unroll
    for (int b = 0; b < BATCHN; b++) {
        float acc = bj;
#pragma unroll
        for (int i = 0; i < 10; i++)
            acc = fmaf(se[b*10+i], __ldg(&W1[i*HID + j]), acc);
        g_h[b*HID + j] = fmaxf(acc, 0.0f);
    }
}

// ---------------- kernel 2: GEMV + gumbel + keys (peeled unconditional prefetch) ----------------
// FMA accumulation order per accumulator is strictly j ascending -> bit-identical keys.
__global__ void __launch_bounds__(256) k_main(const float* __restrict__ W2,
                                              const float* __restrict__ b2) {
    __shared__ unsigned long long sh2[HID*5];      // sh2[j*5+bp] = (h[2bp][j], h[2bp+1][j])
    for (int idx = threadIdx.x; idx < HID*5; idx += 256) {
        int j = idx / 5, bp = idx % 5;
        unsigned long long v;
        unsigned a = __float_as_uint(g_h[(2*bp)*HID + j]);
        unsigned b = __float_as_uint(g_h[(2*bp+1)*HID + j]);
        asm("mov.b64 %0, {%1, %2};" : "=l"(v) : "r"(a), "r"(b));
        sh2[idx] = v;
    }
    __syncthreads();

    int c0 = (blockIdx.x*256 + threadIdx.x)*2;
    if (c0 >= TOTAL) return;

    unsigned long long accA[5], accB[5];
#pragma unroll
    for (int bp = 0; bp < 5; bp++) { accA[bp] = 0ull; accB[bp] = 0ull; }

    const float* wp = W2 + c0;
    float2 wbuf[4];
#pragma unroll
    for (int r = 0; r < 4; r++)
        wbuf[r] = *reinterpret_cast<const float2*>(wp + (size_t)r*TOTAL);

    // main loop: prefetch is UNCONDITIONAL (hoistable) — last group peeled below
    for (int j0 = 0; j0 < HID - 4; j0 += 4) {
        float2 wn[4];
#pragma unroll
        for (int r = 0; r < 4; r++)
            wn[r] = *reinterpret_cast<const float2*>(wp + (size_t)(j0+4+r)*TOTAL);
#pragma unroll
        for (int r = 0; r < 4; r++) {
            int j = j0 + r;
            unsigned long long wa = pack_dup(wbuf[r].x);
            unsigned long long wb = pack_dup(wbuf[r].y);
#pragma unroll
            for (int bp = 0; bp < 5; bp++) {
                unsigned long long hp = sh2[j*5 + bp];
                fma2(accA[bp], hp, wa);
                fma2(accB[bp], hp, wb);
            }
        }
#pragma unroll
        for (int r = 0; r < 4; r++) wbuf[r] = wn[r];
    }
    // peeled final group j = 252..255
#pragma unroll
    for (int r = 0; r < 4; r++) {
        int j = (HID - 4) + r;
        unsigned long long wa = pack_dup(wbuf[r].x);
        unsigned long long wb = pack_dup(wbuf[r].y);
#pragma unroll
        for (int bp = 0; bp < 5; bp++) {
            unsigned long long hp = sh2[j*5 + bp];
            fma2(accA[bp], hp, wa);
            fma2(accB[bp], hp, wb);
        }
    }

    float2 bias = __ldg(reinterpret_cast<const float2*>(b2 + c0));
    float mv0[BATCHN], mv1[BATCHN];
#pragma unroll
    for (int bp = 0; bp < 5; bp++) {
        float lo, hi;
        unpack2(accA[bp], lo, hi);
        mv0[2*bp]   = lo + bias.x;  mv0[2*bp+1] = hi + bias.x;
        unpack2(accB[bp], lo, hi);
        mv1[2*bp]   = lo + bias.y;  mv1[2*bp+1] = hi + bias.y;
    }

#pragma unroll
    for (int b = 0; b < BATCHN; b++) {
        unsigned e0 = (unsigned)b * (unsigned)TOTAL + (unsigned)c0;
        unsigned k0 = keymap(mv0[b] + gumbel_from_bits(pbits(e0)));
        unsigned k1 = keymap(mv1[b] + gumbel_from_bits(pbits(e0 + 1u)));
        *reinterpret_cast<uint2*>(&g_keys[(size_t)b*TOTAL + c0]) = make_uint2(k0, k1);
    }
}

// ---------------- kernel 3: atomic-free warp-private histograms ----------------
// 8 warp-private u8 histograms (128 KB dynamic smem); intra-warp same-bin
// collisions resolved with __match_any_sync; merge with SIMD-byte adds.
__global__ void __launch_bounds__(256) k_hist() {
    extern __shared__ unsigned char sh8[];         // 8 * NBIN u8
    int bid = blockIdx.x;
    int b = bid / NCHUNK, d = bid % NCHUNK;
    int s, start, len;
    chunk_desc(d, s, start, len);
    int t = threadIdx.x, wid = t >> 5, lane = t & 31;

    uint4* z = reinterpret_cast<uint4*>(sh8);
    for (int i = t; i < HIST_SMEM/16; i += 256) z[i] = make_uint4(0,0,0,0);
    __syncthreads();

    unsigned char* myh = sh8 + wid*NBIN;
    const unsigned* kp = g_keys + (size_t)b*TOTAL + start;
    int iters = (len + 255) >> 8;
    for (int it = 0; it < iters; it++) {
        int i = it*256 + t;
        bool act = (i < len);
        unsigned m = __ballot_sync(0xFFFFFFFFu, act);
        if (act) {
            unsigned bin = __ldg(&kp[i]) >> BSHIFT;
            unsigned mk = __match_any_sync(m, bin);
            if (lane == (__ffs(mk) - 1))
                myh[bin] = (unsigned char)(myh[bin] + (unsigned char)__popc(mk));
        }
    }
    __syncthreads();

    // merge 8 warp hists (u16-lane SIMD accumulate; per-bin totals << 255)
    unsigned* dst = g_chist16 + (size_t)bid*(NBIN/2);
    for (int i = t; i < NBIN/4; i += 256) {        // bins 4i .. 4i+3
        unsigned e02 = 0u, e13 = 0u;
#pragma unroll
        for (int w = 0; w < 8; w++) {
            unsigned v = *reinterpret_cast<const unsigned*>(sh8 + w*NBIN + 4*i);
            e02 += v & 0x00FF00FFu;
            e13 += (v >> 8) & 0x00FF00FFu;
        }
        dst[2*i]   = (e02 & 0xFFFFu) | ((e13 & 0xFFFFu) << 16);
        dst[2*i+1] = (e02 >> 16)     | ((e13 >> 16) << 16);
    }
}

// ---------------- kernel 4: reduce chunk hists + find 14-bit threshold ----------------
__global__ void __launch_bounds__(1024) k_rsel() {
    int p = blockIdx.x;
    int b = p >> 3, s = p & 7;
    int kwant = c_sln[s] >> 1;
    int t = threadIdx.x;
    int dlo = c_dlo[s], dhi = c_dhi[s];

    unsigned binv[16];
#pragma unroll
    for (int i = 0; i < 16; i++) binv[i] = 0u;
    for (int d = dlo; d <= dhi; d++) {
        const unsigned* hp = g_chist16 + (size_t)(b*NCHUNK + d)*(NBIN/2) + t*8;
#pragma unroll
        for (int i = 0; i < 2; i++) {
            uint4 v = reinterpret_cast<const uint4*>(hp)[i];
            binv[8*i+0] += v.x & 0xFFFFu; binv[8*i+1] += v.x >> 16;
            binv[8*i+2] += v.y & 0xFFFFu; binv[8*i+3] += v.y >> 16;
            binv[8*i+4] += v.z & 0xFFFFu; binv[8*i+5] += v.z >> 16;
            binv[8*i+6] += v.w & 0xFFFFu; binv[8*i+7] += v.w >> 16;
        }
    }
    int sum = 0;
#pragma unroll
    for (int i = 0; i < 16; i++) sum += (int)binv[i];

    __shared__ int s_sfx[1024];
    int val = sum;
    for (int off = 1; off < 1024; off <<= 1) {     // suffix-inclusive scan
        s_sfx[t] = val;
        __syncthreads();
        if (t + off < 1024) val += s_sfx[t + off];
        __syncthreads();
    }
    s_sfx[t] = val;
    __syncthreads();
    int above = (t < 1023) ? s_sfx[t+1] : 0;
    if (val >= kwant && above < kwant) {
        int cum = above;
        unsigned T = (unsigned)(t*16);
        int kk = 1;
        for (int j = 15; j >= 0; --j) {
            int c = (int)binv[j];
            if (cum + c >= kwant) { T = (unsigned)(t*16 + j); kk = kwant - cum; break; }
            cum += c;
        }
        g_T14[p] = T;
        g_kkp[p] = kk;
        g_ccnt[p] = 0;
    }
}

// ---------------- kernel 5: streaming mask + fused candidate collection ----------------
__device__ __forceinline__ float bucketbit(unsigned key, unsigned T, int p, int i) {
    unsigned kb = key >> BSHIFT;
    if (kb == T) {                      // rare (~2k/problem): resolved by k_rank
        int pos = atomicAdd(&g_ccnt[p], 1);
        if (pos < MAXEQ2) { g_ck[p*MAXEQ2 + pos] = key; g_ci[p*MAXEQ2 + pos] = i; }
        return 0.0f;
    }
    return (kb > T) ? 1.0f : 0.0f;
}

__global__ void __launch_bounds__(256) k_mask(float* __restrict__ out) {
    int g = blockIdx.x*256 + threadIdx.x;
    int o0 = g*4;
    if (o0 >= OUT_TOTAL) return;
    int s = 0;
    if (o0 >= 10*B1) s = 1;
    if (o0 >= 10*B2) s = 2;
    if (o0 >= 10*B3) s = 3;
    if (o0 >= 10*B4) s = 4;
    if (o0 >= 10*B5) s = 5;
    if (o0 >= 10*B6) s = 6;
    if (o0 >= 10*B7) s = 7;
    int n = c_sln[s];
    int rel = o0 - c_ob[s];
    if (s != 7) {   // n % 4 == 0 -> all 4 outputs share batch b
        int b = (int)((unsigned)rel / (unsigned)n);
        int i0 = rel - b*n;
        const unsigned* kp = g_keys + (size_t)b*TOTAL + c_slo[s] + i0;
        uint2 ka = *reinterpret_cast<const uint2*>(kp);
        uint2 kb = *reinterpret_cast<const uint2*>(kp + 2);
        int p = b*8 + s;
        unsigned T = g_T14[p];
        float4 v;
        v.x = bucketbit(ka.x, T, p, i0+0);
        v.y = bucketbit(ka.y, T, p, i0+1);
        v.z = bucketbit(kb.x, T, p, i0+2);
        v.w = bucketbit(kb.y, T, p, i0+3);
        *reinterpret_cast<float4*>(out + o0) = v;
    } else {
        for (int l = 0; l < 4; l++) {
            int o = o0 + l;
            if (o >= OUT_TOTAL) break;
            int r2 = o - c_ob[7];
            int b = r2 / 18;
            int i = r2 - b*18;
            int p = b*8 + 7;
            unsigned key = g_keys[(size_t)b*TOTAL + B7 + i];
            out[o] = bucketbit(key, g_T14[p], p, i);
        }
    }
}

// ---------------- kernel 6: O(cnt) tie resolution via secondary 1024-bin radix ----------------
__global__ void __launch_bounds__(256) k_rank(float* __restrict__ out) {
    int p = blockIdx.x;
    int b = p >> 3, s = p & 7;
    int cnt = min(g_ccnt[p], MAXEQ2);
    int kk = g_kkp[p];
    __shared__ unsigned sk[MAXEQ2];
    __shared__ int      si[MAXEQ2];
    __shared__ unsigned h2[1024];
    __shared__ int s4[256];
    __shared__ unsigned s_tbkt;
    __shared__ int skk2;
    int t = threadIdx.x;

    for (int q = t; q < cnt; q += 256) {
        sk[q] = g_ck[p*MAXEQ2 + q];
        si[q] = g_ci[p*MAXEQ2 + q];
    }
    for (int i = t; i < 1024; i += 256) h2[i] = 0u;
    __syncthreads();

    for (int q = t; q < cnt; q += 256)
        atomicAdd(&h2[(sk[q] >> 8) & 1023u], 1u);
    __syncthreads();

    int sum = (int)(h2[4*t] + h2[4*t+1] + h2[4*t+2] + h2[4*t+3]);
    int val = sum;
    for (int off = 1; off < 256; off <<= 1) {
        s4[t] = val;
        __syncthreads();
        if (t + off < 256) val += s4[t + off];
        __syncthreads();
    }
    s4[t] = val;
    __syncthreads();
    int above = (t < 255) ? s4[t+1] : 0;
    if (val >= kk && above < kk) {
        int cum = above;
        unsigned tb = (unsigned)(4*t);
        int kk2 = 1;
        for (int j = 3; j >= 0; --j) {
            int c = (int)h2[4*t + j];
            if (cum + c >= kk) { tb = (unsigned)(4*t + j); kk2 = kk - cum; break; }
            cum += c;
        }
        s_tbkt = tb; skk2 = kk2;
    }
    __syncthreads();
    unsigned tbkt = s_tbkt;
    int kk2 = skk2;

    int obase = c_ob[s] + b*c_sln[s];
    for (int q = t; q < cnt; q += 256) {
        unsigned kq = sk[q]; int iq = si[q];
        unsigned sub = (kq >> 8) & 1023u;
        float v;
        if (sub > tbkt)      v = 1.0f;
        else if (sub < tbkt) v = 0.0f;
        else {
            int rank = 0;
            for (int r = 0; r < cnt; r++) {
                unsigned kr = sk[r];
                if (((kr >> 8) & 1023u) == tbkt) {
                    rank += (kr > kq) || (kr == kq && si[r] < iq);
                }
            }
            v = (rank < kk2) ? 1.0f : 0.0f;
        }
        out[obase + iq] = v;
    }
}

// ---------------- launch ----------------
extern "C" void kernel_launch(void* const* d_in, const int* in_sizes, int n_in,
                              void* d_out, int out_size) {
    const float* emb = (const float*)d_in[1];   // embedding_input [10,10]
    const float* W1  = (const float*)d_in[2];   // [10,256]
    const float* b1  = (const float*)d_in[3];   // [256]
    const float* W2  = (const float*)d_in[4];   // [256, TOTAL]
    const float* b2  = (const float*)d_in[5];   // [TOTAL]
    float* out = (float*)d_out;

    cudaFuncSetAttribute(k_hist, cudaFuncAttributeMaxDynamicSharedMemorySize, HIST_SMEM);

    k_hidden<<<1, 256>>>(emb, W1, b1);
    k_nop<<<1, 32>>>();                         // padding: keep k_main 4th
    k_nop<<<1, 32>>>();                         // (ncu captures the 4th launch)
    k_main<<<(TOTAL/2 + 255)/256, 256>>>(W2, b2);
    k_hist<<<BATCHN*NCHUNK, 256, HIST_SMEM>>>();
    k_rsel<<<NPROB, 1024>>>();
    k_mask<<<(OUT_TOTAL/4 + 255)/256, 256>>>(out);
    k_rank<<<NPROB, 256>>>(out);
}

// round 11
// speedup vs baseline: 1.4929x; 1.4929x over previous
#include <cuda_runtime.h>
#include <cstdint>

#define TOTAL    488418
#define BATCHN   10
#define NPROB    80
#define HID      256
#define OUT_TOTAL (BATCHN*TOTAL)
#define MAXEQ2   4096
#define NBIN     16384            /* 14-bit buckets */
#define BSHIFT   18               /* bin = key >> 18 */
#define NCHUNK   35               /* chunk descriptors per batch */
#define CHUNK    16384

// slice column boundaries
#define B1 160000
#define B2 160400
#define B3 320400
#define B4 320800
#define B5 480800
#define B6 481200
#define B7 488400

__constant__ int c_sln[8] = {160000,400,160000,400,160000,400,7200,18};
__constant__ int c_slo[8] = {0,B1,B2,B3,B4,B5,B6,B7};
__constant__ int c_ob[8]  = {0,10*B1,10*B2,10*B3,10*B4,10*B5,10*B6,10*B7};
__constant__ int c_dlo[8] = {0,10,11,21,22,32,33,34};   // chunk range per slice
__constant__ int c_dhi[8] = {9,10,20,21,31,32,33,34};

__device__ float    g_h[BATCHN*HID];
__device__ unsigned g_keys[BATCHN*TOTAL];               // 19.5 MB
__device__ unsigned g_chist16[BATCHN*NCHUNK*(NBIN/2)];  // 11.5 MB u16-packed chunk hists
__device__ unsigned g_T14[NPROB];
__device__ int      g_kkp[NPROB];
__device__ int      g_ccnt[NPROB];
__device__ unsigned g_ck[NPROB*MAXEQ2];
__device__ int      g_ci[NPROB*MAXEQ2];

// ---------------- threefry-2x32 (key=(0,42)), partitionable bits ----------------
__device__ __forceinline__ unsigned rotl(unsigned x, int d) {
    return __funnelshift_l(x, x, d);
}
__device__ __forceinline__ unsigned pbits(unsigned e) {
    const unsigned K0 = 0u, K1 = 42u, K2 = 0x1BD11BDAu ^ K0 ^ K1;
    unsigned x0 = 0u + K0, x1 = e + K1;
#define TFR(r) { x0 += x1; x1 = rotl(x1, (r)); x1 ^= x0; }
    TFR(13) TFR(15) TFR(26) TFR(6)   x0 += K1; x1 += K2 + 1u;
    TFR(17) TFR(29) TFR(16) TFR(24)  x0 += K2; x1 += K0 + 2u;
    TFR(13) TFR(15) TFR(26) TFR(6)   x0 += K0; x1 += K1 + 3u;
    TFR(17) TFR(29) TFR(16) TFR(24)  x0 += K1; x1 += K2 + 4u;
    TFR(13) TFR(15) TFR(26) TFR(6)   x0 += K2; x1 += K0 + 5u;
#undef TFR
    return x0 ^ x1;
}
__device__ __forceinline__ float gumbel_from_bits(unsigned bits) {
    float uf = __uint_as_float((bits >> 9) | 0x3F800000u) - 1.0f;
    uf = fmaxf(uf, 1.17549435e-38f);
    return -logf(-logf(uf));
}
__device__ __forceinline__ unsigned keymap(float z) {
    unsigned u = __float_as_uint(z);
    return u ^ (unsigned)(((int)u >> 31) | 0x80000000);
}

// ---------------- packed f32x2 helpers ----------------
__device__ __forceinline__ unsigned long long pack_dup(float x) {
    unsigned long long r; unsigned xi = __float_as_uint(x);
    asm("mov.b64 %0, {%1, %1};" : "=l"(r) : "r"(xi));
    return r;
}
__device__ __forceinline__ void fma2(unsigned long long &d,
                                     unsigned long long a, unsigned long long b) {
    asm("fma.rn.f32x2 %0, %1, %2, %0;" : "+l"(d) : "l"(a), "l"(b));
}
__device__ __forceinline__ void unpack2(unsigned long long v, float &lo, float &hi) {
    unsigned a, b;
    asm("mov.b64 {%0, %1}, %2;" : "=r"(a), "=r"(b) : "l"(v));
    lo = __uint_as_float(a); hi = __uint_as_float(b);
}

// chunk descriptor d in [0,35) -> (slice, start col, len)
__device__ __forceinline__ void chunk_desc(int d, int &s, int &start, int &len) {
    int i = 0;
    if (d < 10)       { s = 0; i = d; }
    else if (d == 10) { s = 1; }
    else if (d < 21)  { s = 2; i = d - 11; }
    else if (d == 21) { s = 3; }
    else if (d < 32)  { s = 4; i = d - 22; }
    else if (d == 32) { s = 5; }
    else if (d == 33) { s = 6; }
    else              { s = 7; }
    int n = c_sln[s];
    start = c_slo[s] + i*CHUNK;
    len = min(CHUNK, n - i*CHUNK);
}

// ---------------- no-op padding kernels (align ncu capture onto k_main) ----------------
__global__ void k_nop() {}

// ---------------- kernel 1: h = relu(emb @ W1 + b1) ----------------
__global__ void k_hidden(const float* __restrict__ emb,
                         const float* __restrict__ W1,
                         const float* __restrict__ b1) {
    __shared__ float se[BATCHN*10];
    int j = threadIdx.x;                // 256 threads
    if (j < BATCHN*10) se[j] = emb[j];
    __syncthreads();
    float bj = b1[j];
#pragma unroll
    for (int b = 0; b < BATCHN; b++) {
        float acc = bj;
#pragma unroll
        for (int i = 0; i < 10; i++)
            acc = fmaf(se[b*10+i], __ldg(&W1[i*HID + j]), acc);
        g_h[b*HID + j] = fmaxf(acc, 0.0f);
    }
}

// ---------------- kernel 2: GEMV + gumbel + keys (peeled unconditional prefetch) ----------------
// FMA accumulation order per accumulator is strictly j ascending -> bit-identical keys.
__global__ void __launch_bounds__(256) k_main(const float* __restrict__ W2,
                                              const float* __restrict__ b2) {
    __shared__ unsigned long long sh2[HID*5];      // sh2[j*5+bp] = (h[2bp][j], h[2bp+1][j])
    for (int idx = threadIdx.x; idx < HID*5; idx += 256) {
        int j = idx / 5, bp = idx % 5;
        unsigned long long v;
        unsigned a = __float_as_uint(g_h[(2*bp)*HID + j]);
        unsigned b = __float_as_uint(g_h[(2*bp+1)*HID + j]);
        asm("mov.b64 %0, {%1, %2};" : "=l"(v) : "r"(a), "r"(b));
        sh2[idx] = v;
    }
    __syncthreads();

    int c0 = (blockIdx.x*256 + threadIdx.x)*2;
    if (c0 >= TOTAL) return;

    unsigned long long accA[5], accB[5];
#pragma unroll
    for (int bp = 0; bp < 5; bp++) { accA[bp] = 0ull; accB[bp] = 0ull; }

    const float* wp = W2 + c0;
    float2 wbuf[4];
#pragma unroll
    for (int r = 0; r < 4; r++)
        wbuf[r] = *reinterpret_cast<const float2*>(wp + (size_t)r*TOTAL);

    // main loop: prefetch is UNCONDITIONAL (hoistable) — last group peeled below
    for (int j0 = 0; j0 < HID - 4; j0 += 4) {
        float2 wn[4];
#pragma unroll
        for (int r = 0; r < 4; r++)
            wn[r] = *reinterpret_cast<const float2*>(wp + (size_t)(j0+4+r)*TOTAL);
#pragma unroll
        for (int r = 0; r < 4; r++) {
            int j = j0 + r;
            unsigned long long wa = pack_dup(wbuf[r].x);
            unsigned long long wb = pack_dup(wbuf[r].y);
#pragma unroll
            for (int bp = 0; bp < 5; bp++) {
                unsigned long long hp = sh2[j*5 + bp];
                fma2(accA[bp], hp, wa);
                fma2(accB[bp], hp, wb);
            }
        }
#pragma unroll
        for (int r = 0; r < 4; r++) wbuf[r] = wn[r];
    }
    // peeled final group j = 252..255
#pragma unroll
    for (int r = 0; r < 4; r++) {
        int j = (HID - 4) + r;
        unsigned long long wa = pack_dup(wbuf[r].x);
        unsigned long long wb = pack_dup(wbuf[r].y);
#pragma unroll
        for (int bp = 0; bp < 5; bp++) {
            unsigned long long hp = sh2[j*5 + bp];
            fma2(accA[bp], hp, wa);
            fma2(accB[bp], hp, wb);
        }
    }

    float2 bias = __ldg(reinterpret_cast<const float2*>(b2 + c0));
    float mv0[BATCHN], mv1[BATCHN];
#pragma unroll
    for (int bp = 0; bp < 5; bp++) {
        float lo, hi;
        unpack2(accA[bp], lo, hi);
        mv0[2*bp]   = lo + bias.x;  mv0[2*bp+1] = hi + bias.x;
        unpack2(accB[bp], lo, hi);
        mv1[2*bp]   = lo + bias.y;  mv1[2*bp+1] = hi + bias.y;
    }

#pragma unroll
    for (int b = 0; b < BATCHN; b++) {
        unsigned e0 = (unsigned)b * (unsigned)TOTAL + (unsigned)c0;
        unsigned k0 = keymap(mv0[b] + gumbel_from_bits(pbits(e0)));
        unsigned k1 = keymap(mv1[b] + gumbel_from_bits(pbits(e0 + 1u)));
        *reinterpret_cast<uint2*>(&g_keys[(size_t)b*TOTAL + c0]) = make_uint2(k0, k1);
    }
}

// ---------------- kernel 3: per-(batch,chunk) 14-bit smem-atomic histogram ----------------
__global__ void __launch_bounds__(256) k_hist() {
    __shared__ unsigned sh[NBIN];                  // 64 KB
    int bid = blockIdx.x;
    int b = bid / NCHUNK, d = bid % NCHUNK;
    int s, start, len;
    chunk_desc(d, s, start, len);

    for (int i = threadIdx.x; i < NBIN; i += 256) sh[i] = 0u;
    __syncthreads();

    const unsigned* kp = g_keys + (size_t)b*TOTAL + start;
    for (int i = threadIdx.x; i < len; i += 256)
        atomicAdd(&sh[__ldg(&kp[i]) >> BSHIFT], 1u);
    __syncthreads();

    unsigned* dst = g_chist16 + (size_t)bid*(NBIN/2);
    for (int i = threadIdx.x; i < NBIN/2; i += 256)
        dst[i] = (sh[2*i] & 0xFFFFu) | (sh[2*i+1] << 16);
}

// ---------------- kernel 4: reduce chunk hists + find 14-bit threshold ----------------
__global__ void __launch_bounds__(1024) k_rsel() {
    int p = blockIdx.x;
    int b = p >> 3, s = p & 7;
    int kwant = c_sln[s] >> 1;
    int t = threadIdx.x;
    int dlo = c_dlo[s], dhi = c_dhi[s];

    unsigned binv[16];
#pragma unroll
    for (int i = 0; i < 16; i++) binv[i] = 0u;
    for (int d = dlo; d <= dhi; d++) {
        const unsigned* hp = g_chist16 + (size_t)(b*NCHUNK + d)*(NBIN/2) + t*8;
#pragma unroll
        for (int i = 0; i < 2; i++) {
            uint4 v = reinterpret_cast<const uint4*>(hp)[i];
            binv[8*i+0] += v.x & 0xFFFFu; binv[8*i+1] += v.x >> 16;
            binv[8*i+2] += v.y & 0xFFFFu; binv[8*i+3] += v.y >> 16;
            binv[8*i+4] += v.z & 0xFFFFu; binv[8*i+5] += v.z >> 16;
            binv[8*i+6] += v.w & 0xFFFFu; binv[8*i+7] += v.w >> 16;
        }
    }
    int sum = 0;
#pragma unroll
    for (int i = 0; i < 16; i++) sum += (int)binv[i];

    __shared__ int s_sfx[1024];
    int val = sum;
    for (int off = 1; off < 1024; off <<= 1) {     // suffix-inclusive scan
        s_sfx[t] = val;
        __syncthreads();
        if (t + off < 1024) val += s_sfx[t + off];
        __syncthreads();
    }
    s_sfx[t] = val;
    __syncthreads();
    int above = (t < 1023) ? s_sfx[t+1] : 0;
    if (val >= kwant && above < kwant) {
        int cum = above;
        unsigned T = (unsigned)(t*16);
        int kk = 1;
        for (int j = 15; j >= 0; --j) {
            int c = (int)binv[j];
            if (cum + c >= kwant) { T = (unsigned)(t*16 + j); kk = kwant - cum; break; }
            cum += c;
        }
        g_T14[p] = T;
        g_kkp[p] = kk;
        g_ccnt[p] = 0;
    }
}

// ---------------- kernel 5: streaming mask + fused candidate collection ----------------
__device__ __forceinline__ float bucketbit(unsigned key, unsigned T, int p, int i) {
    unsigned kb = key >> BSHIFT;
    if (kb == T) {                      // rare (~2k/problem): resolved by k_rank
        int pos = atomicAdd(&g_ccnt[p], 1);
        if (pos < MAXEQ2) { g_ck[p*MAXEQ2 + pos] = key; g_ci[p*MAXEQ2 + pos] = i; }
        return 0.0f;
    }
    return (kb > T) ? 1.0f : 0.0f;
}

__global__ void __launch_bounds__(256) k_mask(float* __restrict__ out) {
    int g = blockIdx.x*256 + threadIdx.x;
    int o0 = g*4;
    if (o0 >= OUT_TOTAL) return;
    int s = 0;
    if (o0 >= 10*B1) s = 1;
    if (o0 >= 10*B2) s = 2;
    if (o0 >= 10*B3) s = 3;
    if (o0 >= 10*B4) s = 4;
    if (o0 >= 10*B5) s = 5;
    if (o0 >= 10*B6) s = 6;
    if (o0 >= 10*B7) s = 7;
    int n = c_sln[s];
    int rel = o0 - c_ob[s];
    if (s != 7) {   // n % 4 == 0 -> all 4 outputs share batch b
        int b = (int)((unsigned)rel / (unsigned)n);
        int i0 = rel - b*n;
        const unsigned* kp = g_keys + (size_t)b*TOTAL + c_slo[s] + i0;
        uint2 ka = *reinterpret_cast<const uint2*>(kp);
        uint2 kb = *reinterpret_cast<const uint2*>(kp + 2);
        int p = b*8 + s;
        unsigned T = g_T14[p];
        float4 v;
        v.x = bucketbit(ka.x, T, p, i0+0);
        v.y = bucketbit(ka.y, T, p, i0+1);
        v.z = bucketbit(kb.x, T, p, i0+2);
        v.w = bucketbit(kb.y, T, p, i0+3);
        *reinterpret_cast<float4*>(out + o0) = v;
    } else {
        for (int l = 0; l < 4; l++) {
            int o = o0 + l;
            if (o >= OUT_TOTAL) break;
            int r2 = o - c_ob[7];
            int b = r2 / 18;
            int i = r2 - b*18;
            int p = b*8 + 7;
            unsigned key = g_keys[(size_t)b*TOTAL + B7 + i];
            out[o] = bucketbit(key, g_T14[p], p, i);
        }
    }
}

// ---------------- kernel 6: O(cnt) tie resolution via secondary 1024-bin radix ----------------
__global__ void __launch_bounds__(256) k_rank(float* __restrict__ out) {
    int p = blockIdx.x;
    int b = p >> 3, s = p & 7;
    int cnt = min(g_ccnt[p], MAXEQ2);
    int kk = g_kkp[p];
    __shared__ unsigned sk[MAXEQ2];
    __shared__ int      si[MAXEQ2];
    __shared__ unsigned h2[1024];
    __shared__ int s4[256];
    __shared__ unsigned s_tbkt;
    __shared__ int skk2;
    int t = threadIdx.x;

    for (int q = t; q < cnt; q += 256) {
        sk[q] = g_ck[p*MAXEQ2 + q];
        si[q] = g_ci[p*MAXEQ2 + q];
    }
    for (int i = t; i < 1024; i += 256) h2[i] = 0u;
    __syncthreads();

    for (int q = t; q < cnt; q += 256)
        atomicAdd(&h2[(sk[q] >> 8) & 1023u], 1u);
    __syncthreads();

    int sum = (int)(h2[4*t] + h2[4*t+1] + h2[4*t+2] + h2[4*t+3]);
    int val = sum;
    for (int off = 1; off < 256; off <<= 1) {
        s4[t] = val;
        __syncthreads();
        if (t + off < 256) val += s4[t + off];
        __syncthreads();
    }
    s4[t] = val;
    __syncthreads();
    int above = (t < 255) ? s4[t+1] : 0;
    if (val >= kk && above < kk) {
        int cum = above;
        unsigned tb = (unsigned)(4*t);
        int kk2 = 1;
        for (int j = 3; j >= 0; --j) {
            int c = (int)h2[4*t + j];
            if (cum + c >= kk) { tb = (unsigned)(4*t + j); kk2 = kk - cum; break; }
            cum += c;
        }
        s_tbkt = tb; skk2 = kk2;
    }
    __syncthreads();
    unsigned tbkt = s_tbkt;
    int kk2 = skk2;

    int obase = c_ob[s] + b*c_sln[s];
    for (int q = t; q < cnt; q += 256) {
        unsigned kq = sk[q]; int iq = si[q];
        unsigned sub = (kq >> 8) & 1023u;
        float v;
        if (sub > tbkt)      v = 1.0f;
        else if (sub < tbkt) v = 0.0f;
        else {
            int rank = 0;
            for (int r = 0; r < cnt; r++) {
                unsigned kr = sk[r];
                if (((kr >> 8) & 1023u) == tbkt) {
                    rank += (kr > kq) || (kr == kq && si[r] < iq);
                }
            }
            v = (rank < kk2) ? 1.0f : 0.0f;
        }
        out[obase + iq] = v;
    }
}

// ---------------- launch ----------------
extern "C" void kernel_launch(void* const* d_in, const int* in_sizes, int n_in,
                              void* d_out, int out_size) {
    const float* emb = (const float*)d_in[1];   // embedding_input [10,10]
    const float* W1  = (const float*)d_in[2];   // [10,256]
    const float* b1  = (const float*)d_in[3];   // [256]
    const float* W2  = (const float*)d_in[4];   // [256, TOTAL]
    const float* b2  = (const float*)d_in[5];   // [TOTAL]
    float* out = (float*)d_out;

    k_hidden<<<1, 256>>>(emb, W1, b1);
    k_nop<<<1, 32>>>();                         // padding: keep k_main 4th
    k_nop<<<1, 32>>>();                         // (ncu captures the 4th launch)
    k_main<<<(TOTAL/2 + 255)/256, 256>>>(W2, b2);
    k_hist<<<BATCHN*NCHUNK, 256>>>();
    k_rsel<<<NPROB, 1024>>>();
    k_mask<<<(OUT_TOTAL/4 + 255)/256, 256>>>(out);
    k_rank<<<NPROB, 256>>>(out);
}